// round 9
// baseline (speedup 1.0000x reference)
#include <cuda_runtime.h>
#include <cuda_fp16.h>
#include <cstdint>
#include <cstddef>

// Problem sizes
#define BB   8192
#define II   1024
#define HH   1024
#define KK   2048          // I + H
#define NNP  4096          // 4*H packed (gate-interleaved)
// GEMM tiling: CTA 128x128, 4 warps of 64x64, 2 CTAs/SM
#define BM   128
#define BN   128
#define BK   64            // fp16 elems per chunk (= 128 bytes per row)
#define NCHUNK (KK / BK)   // 32
#define THREADS 128
#define NSTAGE 3
#define ASTAGE_BYTES (BM * BK * 2)          // 16384
#define BSTAGE_BYTES (BN * BK * 2)          // 16384
#define STAGE_BYTES  (ASTAGE_BYTES + BSTAGE_BYTES)   // 32768
#define DYN_SMEM (NSTAGE * STAGE_BYTES)              // 98304

// Packed fp16 operands
__device__ __half g_At[(size_t)BB * KK];   // [m][k] rows of [x | h]
__device__ __half g_Wt[(size_t)NNP * KK];  // [np][k], np = 4*j + gate

// ---------------------------------------------------------------- helpers ---
__device__ __forceinline__ uint32_t smem_u32(const void* p) {
    uint32_t a;
    asm("{ .reg .u64 t; cvta.to.shared.u64 t, %1; cvt.u32.u64 %0, t; }"
        : "=r"(a) : "l"(p));
    return a;
}
__device__ __forceinline__ void cp_async16(uint32_t saddr, const void* gaddr) {
    asm volatile("cp.async.cg.shared.global [%0], [%1], 16;"
                 :: "r"(saddr), "l"(gaddr) : "memory");
}
__device__ __forceinline__ void cp_async_arrive_noinc(uint32_t mbar) {
    asm volatile("cp.async.mbarrier.arrive.noinc.shared.b64 [%0];"
                 :: "r"(mbar) : "memory");
}
__device__ __forceinline__ void mbar_init(uint32_t addr, uint32_t cnt) {
    asm volatile("mbarrier.init.shared.b64 [%0], %1;" :: "r"(addr), "r"(cnt) : "memory");
}
__device__ __forceinline__ void mbar_arrive(uint32_t addr) {
    asm volatile("mbarrier.arrive.shared.b64 _, [%0];" :: "r"(addr) : "memory");
}
__device__ __forceinline__ void mbar_wait(uint32_t addr, uint32_t parity) {
    asm volatile(
        "{\n\t"
        ".reg .pred P1;\n\t"
        "LAB_WAIT_%=:\n\t"
        "mbarrier.try_wait.parity.acquire.cta.shared::cta.b64 P1, [%0], %1, 0x989680;\n\t"
        "@P1 bra LAB_DONE_%=;\n\t"
        "bra LAB_WAIT_%=;\n\t"
        "LAB_DONE_%=:\n\t"
        "}"
        :: "r"(addr), "r"(parity) : "memory");
}
__device__ __forceinline__ void ldmatrix_x4(uint32_t* r, uint32_t addr) {
    asm volatile("ldmatrix.sync.aligned.m8n8.x4.shared.b16 {%0,%1,%2,%3}, [%4];"
                 : "=r"(r[0]), "=r"(r[1]), "=r"(r[2]), "=r"(r[3]) : "r"(addr));
}
__device__ __forceinline__ void mma_fp16(float* d, const uint32_t* a, const uint32_t* b) {
    asm volatile(
        "mma.sync.aligned.m16n8k16.row.col.f32.f16.f16.f32 "
        "{%0,%1,%2,%3}, {%4,%5,%6,%7}, {%8,%9}, {%0,%1,%2,%3};"
        : "+f"(d[0]), "+f"(d[1]), "+f"(d[2]), "+f"(d[3])
        : "r"(a[0]), "r"(a[1]), "r"(a[2]), "r"(a[3]), "r"(b[0]), "r"(b[1]));
}
__device__ __forceinline__ float tanh_fast(float x) {
    float y;
    asm("tanh.approx.f32 %0, %1;" : "=f"(y) : "f"(x));
    return y;
}
__device__ __forceinline__ float sigmoid_fast(float v) {
    return fmaf(0.5f, tanh_fast(0.5f * v), 0.5f);
}

// --------------------------------------------------------- fused pack kernel
#define PACKA_BLOCKS (BB * (KK / 8) / 256)          // 8192
#define PACKW_BLOCKS ((KK / 64) * (NNP / 32))       // 4096
__global__ void pack_fused_kernel(const float* __restrict__ x,
                                  const float* __restrict__ h,
                                  const float* __restrict__ Wx,
                                  const float* __restrict__ Wh) {
    __shared__ float tile[32][65];
    const int tid = threadIdx.x;
    if (blockIdx.x < PACKA_BLOCKS) {
        // ---- A pack: g_At[m][k] = fp16( k<1024 ? x : h ) ----
        const int u = blockIdx.x * 256 + tid;     // 8-elem unit
        const int row = u >> 8;                   // 256 units per row
        const int k0 = (u & 255) * 8;
        const float* src = (k0 < II) ? (x + (size_t)row * II + k0)
                                     : (h + (size_t)row * HH + (k0 - II));
        const float4 v0 = *reinterpret_cast<const float4*>(src);
        const float4 v1 = *reinterpret_cast<const float4*>(src + 4);
        __half2 o[4];
        o[0] = __floats2half2_rn(v0.x, v0.y);
        o[1] = __floats2half2_rn(v0.z, v0.w);
        o[2] = __floats2half2_rn(v1.x, v1.y);
        o[3] = __floats2half2_rn(v1.z, v1.w);
        *reinterpret_cast<uint4*>(&g_At[(size_t)row * KK + k0]) =
            *reinterpret_cast<const uint4*>(o);
    } else {
        // ---- W pack: tile 64k x 32c, write coalesced half2 rows ----
        const int wb = blockIdx.x - PACKA_BLOCKS;
        const int k0 = (wb & 31) * 64;            // 32 k-tiles
        const int c0 = (wb >> 5) * 32;            // 128 c-tiles
        #pragma unroll
        for (int i = 0; i < 8; i++) {
            const int idx = tid + 256 * i;        // 0..2047
            const int cl = idx & 31;
            const int kl = idx >> 5;              // 0..63
            const int k = k0 + kl;
            const int c = c0 + cl;
            tile[cl][kl] = (k < II) ? Wx[(size_t)k * NNP + c]
                                    : Wh[(size_t)(k - II) * NNP + c];
        }
        __syncthreads();
        #pragma unroll
        for (int i = 0; i < 4; i++) {
            const int idx = tid + 256 * i;        // 0..1023
            const int k2 = idx & 31;              // half2 unit within row
            const int cl = idx >> 5;              // 0..31
            const int c = c0 + cl;
            const int g = c >> 10;
            const int j = c & 1023;
            const int np = 4 * j + g;
            const __half2 hv = __floats2half2_rn(tile[cl][2 * k2], tile[cl][2 * k2 + 1]);
            *reinterpret_cast<__half2*>(&g_Wt[(size_t)np * KK + k0 + 2 * k2]) = hv;
        }
    }
}

// ------------------------------------------------------------ GEMM kernel ---
// mbarrier pipeline, software-pipelined ACROSS chunk boundaries:
// the full-wait for chunk kc+1 and its s0 fragment loads are issued while
// chunk kc's last two mma_all batches are still queued in the tensor pipe.
// mbars: [0..2] full[s] (cnt 128, async arrivals), [3..5] free[s] (cnt 4),
//        [6] cin ready (cnt 128, async arrivals)
__global__ __launch_bounds__(THREADS, 2) void lstm_gemm_kernel(
    const float* __restrict__ cin, const float* __restrict__ bx,
    float* __restrict__ out, int write_c) {
    extern __shared__ char dynsmem[];
    __shared__ __align__(8) uint64_t s_mb[7];
    const uint32_t sbase = smem_u32(dynsmem);
    const uint32_t mb0 = smem_u32(&s_mb[0]);

    const int tid = threadIdx.x;
    const int wid = tid >> 5;
    const int lane = tid & 31;
    const int tn = blockIdx.x;       // N tile (0..31), 128 packed cols
    const int tm = blockIdx.y;       // M tile (0..63)
    const int row0 = tm * BM;
    const int n0 = tn * BN;

    if (tid == 0) {
        #pragma unroll
        for (int s = 0; s < 3; s++) mbar_init(mb0 + 8 * s, 128);        // full
        #pragma unroll
        for (int s = 0; s < 3; s++) mbar_init(mb0 + 8 * (3 + s), 4);    // free
        mbar_init(mb0 + 8 * 6, 128);                                    // cin
    }
    __syncthreads();

    float acc[4][8][4] = {};          // warp tile 64x64

    // ---- producer: fill kf (stage kf%3); kf==NCHUNK fills cin into stage 2 ----
    auto producer = [&](int kf) {
        if (kf < NCHUNK) {
            const int st = kf % NSTAGE;
            if (kf >= NSTAGE) mbar_wait(mb0 + 8 * (3 + st), (uint32_t)((kf / NSTAGE - 1) & 1));
            const uint32_t sa = sbase + st * STAGE_BYTES;
            const uint32_t sb = sa + ASTAGE_BYTES;
            const __half* gA = g_At + (size_t)row0 * KK + kf * BK;
            #pragma unroll
            for (int i = 0; i < 8; i++) {
                const int idx = tid + THREADS * i;   // 0..1023 (128 rows x 8 units)
                const int r = idx >> 3, uu = idx & 7;
                cp_async16(sa + r * 128 + ((uu ^ (r & 7)) << 4),
                           gA + (size_t)r * KK + uu * 8);
            }
            const __half* gB = g_Wt + (size_t)n0 * KK + kf * BK;
            #pragma unroll
            for (int i = 0; i < 8; i++) {
                const int idx = tid + THREADS * i;
                const int r = idx >> 3, uu = idx & 7;
                cp_async16(sb + r * 128 + ((uu ^ (r & 7)) << 4),
                           gB + (size_t)r * KK + uu * 8);
            }
            cp_async_arrive_noinc(mb0 + 8 * st);
        } else if (kf == NCHUNK) {
            // cin tile [128][32] f32 into stage-2 region (dead after use kc=29)
            mbar_wait(mb0 + 8 * (3 + 2), (uint32_t)((NCHUNK / NSTAGE - 1) & 1));
            const uint32_t cb = sbase + 2 * STAGE_BYTES;
            const float* gC = cin + (size_t)row0 * HH + tn * 32;
            #pragma unroll
            for (int i = 0; i < 8; i++) {
                const int v = tid + THREADS * i;     // 0..1023 (128 rows x 8 units)
                const int r = v >> 3, uu = v & 7;
                cp_async16(cb + r * 128 + ((uu ^ (r & 7)) << 4),
                           gC + (size_t)r * HH + uu * 4);
            }
            cp_async_arrive_noinc(mb0 + 8 * 6);
        }
    };

    producer(0);
    producer(1);

    const int wm0 = (wid >> 1) * 64;   // warp M origin (0 or 64)
    const int wn0 = (wid & 1) * 64;    // warp N origin (0 or 64)
    const int lsel = lane >> 3;        // ldmatrix matrix id (0..3)
    const int lrow8 = lane & 7;        // row within 8x8 matrix

    auto load_frags = [&](uint32_t sa, uint32_t sb, int s,
                          uint32_t (*afr)[4], uint32_t (*bfr)[4]) {
        #pragma unroll
        for (int mi = 0; mi < 4; mi++) {
            const int r = wm0 + mi * 16 + (lsel & 1) * 8 + lrow8;
            const uint32_t ku = (uint32_t)(s * 2 + (lsel >> 1));
            ldmatrix_x4(afr[mi], sa + r * 128 + ((ku ^ (uint32_t)(r & 7)) << 4));
        }
        #pragma unroll
        for (int fp = 0; fp < 4; fp++) {
            const int rn = wn0 + fp * 16 + (lsel >> 1) * 8 + lrow8;
            const uint32_t ku = (uint32_t)(s * 2 + (lsel & 1));
            ldmatrix_x4(bfr[fp], sb + rn * 128 + ((ku ^ (uint32_t)(rn & 7)) << 4));
        }
    };
    auto mma_all = [&](uint32_t (*afr)[4], uint32_t (*bfr)[4]) {
        #pragma unroll
        for (int mi = 0; mi < 4; mi++)
            #pragma unroll
            for (int f = 0; f < 8; f++)
                mma_fp16(acc[mi][f], afr[mi], &bfr[f >> 1][(f & 1) * 2]);
    };

    uint32_t afr[2][4][4];
    uint32_t bfr[2][4][4];

    // prologue: wait chunk 0 and preload its s0 fragments
    mbar_wait(mb0 + 0, 0u);
    load_frags(sbase, sbase + ASTAGE_BYTES, 0, afr[0], bfr[0]);

    #pragma unroll 1
    for (int kc = 0; kc < NCHUNK; kc++) {
        const int st = kc % NSTAGE;
        const uint32_t sa = sbase + st * STAGE_BYTES;
        const uint32_t sb = sa + ASTAGE_BYTES;

        load_frags(sa, sb, 1, afr[1], bfr[1]);
        mma_all(afr[0], bfr[0]);                 // s0
        producer(kc + 2);                        // free-wait hidden under s0 MMAs
        load_frags(sa, sb, 2, afr[0], bfr[0]);
        mma_all(afr[1], bfr[1]);                 // s1
        load_frags(sa, sb, 3, afr[1], bfr[1]);
        mma_all(afr[0], bfr[0]);                 // s2
        if (lane == 0) mbar_arrive(mb0 + 8 * (3 + st));   // stage reads done
        if (kc + 1 < NCHUNK)                     // early wait: hidden under s2 MMAs
            mbar_wait(mb0 + 8 * ((kc + 1) % NSTAGE),
                      (uint32_t)(((kc + 1) / NSTAGE) & 1));
        mma_all(afr[1], bfr[1]);                 // s3
        if (kc + 1 < NCHUNK) {                   // next-chunk s0: hidden under s3 MMAs
            const uint32_t sa1 = sbase + ((kc + 1) % NSTAGE) * STAGE_BYTES;
            load_frags(sa1, sa1 + ASTAGE_BYTES, 0, afr[0], bfr[0]);
        }
    }

    mbar_wait(mb0 + 8 * 6, 0u);   // cin prefetch complete
    __syncthreads();              // all warps done with stages 0/1 before reuse

    // ---- fused LSTM epilogue ----
    float* smf = reinterpret_cast<float*>(dynsmem);   // h_s[128][33], c_s[128][33]
    const float* cin_s = reinterpret_cast<const float*>(dynsmem + 2 * STAGE_BYTES);
    const int odd = lane & 1;
    #pragma unroll
    for (int mi = 0; mi < 4; mi++) {
        #pragma unroll
        for (int f = 0; f < 8; f++) {
            const float c0 = acc[mi][f][0], c1 = acc[mi][f][1];
            const float c2 = acc[mi][f][2], c3 = acc[mi][f][3];
            const float x0 = __shfl_xor_sync(0xffffffffu, c0, 1);
            const float x1 = __shfl_xor_sync(0xffffffffu, c1, 1);
            const float x2 = __shfl_xor_sync(0xffffffffu, c2, 1);
            const float x3 = __shfl_xor_sync(0xffffffffu, c3, 1);
            // even lane: own (i,f), partner's (g,o); odd lane: row+8, own (g,o)
            const int lrow = wm0 + mi * 16 + (lane >> 2) + (odd ? 8 : 0);
            const int jc = (wn0 >> 2) + f * 2 + ((lane & 3) >> 1);  // 0..31
            const int j = tn * 32 + jc;
            float gi = (odd ? x2 : c0) + bx[j];
            float gf = (odd ? x3 : c1) + bx[HH + j];
            float gg = (odd ? c2 : x0) + bx[2 * HH + j];
            float go = (odd ? c3 : x1) + bx[3 * HH + j];
            const float iv = sigmoid_fast(gi);
            const float fv = sigmoid_fast(gf);
            const float gv = tanh_fast(gg);
            const float ov = sigmoid_fast(go);
            // swizzled cin read (matches cp.async 16B-unit swizzle)
            const int u2 = jc >> 2;
            const float cv = cin_s[lrow * 32 + (((u2 ^ (lrow & 7)) << 2) | (jc & 3))];
            const float cn = fv * cv + iv * gv;
            const float hn = ov * tanh_fast(cn);
            smf[lrow * 33 + jc] = hn;
            smf[128 * 33 + lrow * 33 + jc] = cn;
        }
    }
    __syncthreads();

    // coalesced writeback (128 rows x 32 cols)
    #pragma unroll 1
    for (int i = tid; i < 128 * 32; i += THREADS) {
        const int r = i >> 5, jj = i & 31;
        out[(size_t)(row0 + r) * HH + tn * 32 + jj] = smf[r * 33 + jj];
    }
    if (write_c) {
        #pragma unroll 1
        for (int i = tid; i < 128 * 32; i += THREADS) {
            const int r = i >> 5, jj = i & 31;
            out[(size_t)BB * HH + (size_t)(row0 + r) * HH + tn * 32 + jj] =
                smf[128 * 33 + r * 33 + jj];
        }
    }
}

// ------------------------------------------------------------------ launch ---
extern "C" void kernel_launch(void* const* d_in, const int* in_sizes, int n_in,
                              void* d_out, int out_size) {
    const float* x  = (const float*)d_in[0];
    const float* h  = (const float*)d_in[1];
    const float* c  = (const float*)d_in[2];
    const float* Wx = (const float*)d_in[3];
    const float* bx = (const float*)d_in[4];
    const float* Wh = (const float*)d_in[5];
    float* out = (float*)d_out;
    (void)in_sizes; (void)n_in;

    const int write_c = (out_size >= 2 * BB * HH) ? 1 : 0;

    // 1) fused pack: A->fp16, W->fp16 transposed + gate-interleaved
    pack_fused_kernel<<<PACKA_BLOCKS + PACKW_BLOCKS, 256>>>(x, h, Wx, Wh);

    // 2) fp16 mma.sync GEMM, cross-chunk software pipeline, fused LSTM epilogue
    static int attr_set = 0;
    if (!attr_set) {
        cudaFuncSetAttribute(lstm_gemm_kernel,
                             cudaFuncAttributeMaxDynamicSharedMemorySize, DYN_SMEM);
        attr_set = 1;
    }
    lstm_gemm_kernel<<<dim3(NNP / BN, BB / BM), THREADS, DYN_SMEM>>>(c, bx, out, write_c);
}

// round 11
// speedup vs baseline: 1.5391x; 1.5391x over previous
#include <cuda_runtime.h>
#include <cuda_fp16.h>
#include <cstdint>
#include <cstddef>

// Problem sizes
#define BB   8192
#define II   1024
#define HH   1024
#define KK   2048          // I + H
#define NNP  4096          // 4*H packed (gate-interleaved)
// GEMM tiling: CTA 128x128, 4 warps of 64x64, 2 CTAs/SM
#define BM   128
#define BN   128
#define BK   64            // fp16 elems per chunk (= 128 bytes per row)
#define NCHUNK (KK / BK)   // 32
#define THREADS 128
#define NSTAGE 3
#define ASTAGE_BYTES (BM * BK * 2)          // 16384
#define BSTAGE_BYTES (BN * BK * 2)          // 16384
#define STAGE_BYTES  (ASTAGE_BYTES + BSTAGE_BYTES)   // 32768
#define DYN_SMEM (NSTAGE * STAGE_BYTES)              // 98304

// Packed fp16 operands
__device__ __half g_At[(size_t)BB * KK];   // [m][k] rows of [x | h]
__device__ __half g_Wt[(size_t)NNP * KK];  // [np][k], np = 4*j + gate

// ---------------------------------------------------------------- helpers ---
__device__ __forceinline__ uint32_t smem_u32(const void* p) {
    uint32_t a;
    asm("{ .reg .u64 t; cvta.to.shared.u64 t, %1; cvt.u32.u64 %0, t; }"
        : "=r"(a) : "l"(p));
    return a;
}
__device__ __forceinline__ void cp_async16(uint32_t saddr, const void* gaddr) {
    asm volatile("cp.async.cg.shared.global [%0], [%1], 16;"
                 :: "r"(saddr), "l"(gaddr) : "memory");
}
__device__ __forceinline__ void cp_async_arrive_noinc(uint32_t mbar) {
    asm volatile("cp.async.mbarrier.arrive.noinc.shared.b64 [%0];"
                 :: "r"(mbar) : "memory");
}
__device__ __forceinline__ void mbar_init(uint32_t addr, uint32_t cnt) {
    asm volatile("mbarrier.init.shared.b64 [%0], %1;" :: "r"(addr), "r"(cnt) : "memory");
}
__device__ __forceinline__ void mbar_arrive(uint32_t addr) {
    asm volatile("mbarrier.arrive.shared.b64 _, [%0];" :: "r"(addr) : "memory");
}
__device__ __forceinline__ void mbar_wait(uint32_t addr, uint32_t parity) {
    asm volatile(
        "{\n\t"
        ".reg .pred P1;\n\t"
        "LAB_WAIT_%=:\n\t"
        "mbarrier.try_wait.parity.acquire.cta.shared::cta.b64 P1, [%0], %1, 0x989680;\n\t"
        "@P1 bra LAB_DONE_%=;\n\t"
        "bra LAB_WAIT_%=;\n\t"
        "LAB_DONE_%=:\n\t"
        "}"
        :: "r"(addr), "r"(parity) : "memory");
}
__device__ __forceinline__ void ldmatrix_x4(uint32_t* r, uint32_t addr) {
    asm volatile("ldmatrix.sync.aligned.m8n8.x4.shared.b16 {%0,%1,%2,%3}, [%4];"
                 : "=r"(r[0]), "=r"(r[1]), "=r"(r[2]), "=r"(r[3]) : "r"(addr));
}
__device__ __forceinline__ void mma_fp16(float* d, const uint32_t* a, const uint32_t* b) {
    asm volatile(
        "mma.sync.aligned.m16n8k16.row.col.f32.f16.f16.f32 "
        "{%0,%1,%2,%3}, {%4,%5,%6,%7}, {%8,%9}, {%0,%1,%2,%3};"
        : "+f"(d[0]), "+f"(d[1]), "+f"(d[2]), "+f"(d[3])
        : "r"(a[0]), "r"(a[1]), "r"(a[2]), "r"(a[3]), "r"(b[0]), "r"(b[1]));
}
__device__ __forceinline__ float tanh_fast(float x) {
    float y;
    asm("tanh.approx.f32 %0, %1;" : "=f"(y) : "f"(x));
    return y;
}
__device__ __forceinline__ float sigmoid_fast(float v) {
    return fmaf(0.5f, tanh_fast(0.5f * v), 0.5f);
}

// --------------------------------------------------------- fused pack kernel
#define PACKA_BLOCKS (BB * (KK / 16) / 256)         // 4096 (2 units/thread)
#define PACKW_BLOCKS ((KK / 64) * (NNP / 32))       // 4096
__global__ void pack_fused_kernel(const float* __restrict__ x,
                                  const float* __restrict__ h,
                                  const float* __restrict__ Wx,
                                  const float* __restrict__ Wh) {
    __shared__ float tile[32][65];
    const int tid = threadIdx.x;
    if (blockIdx.x < PACKA_BLOCKS) {
        // ---- A pack: 2x 8-elem units per thread (ILP 2) ----
        const int u0 = (blockIdx.x * 256 + tid) * 2;
        #pragma unroll
        for (int uu = 0; uu < 2; uu++) {
            const int u = u0 + uu;
            const int row = u >> 8;                   // 256 units per row
            const int k0 = (u & 255) * 8;
            const float* src = (k0 < II) ? (x + (size_t)row * II + k0)
                                         : (h + (size_t)row * HH + (k0 - II));
            const float4 v0 = *reinterpret_cast<const float4*>(src);
            const float4 v1 = *reinterpret_cast<const float4*>(src + 4);
            __half2 o[4];
            o[0] = __floats2half2_rn(v0.x, v0.y);
            o[1] = __floats2half2_rn(v0.z, v0.w);
            o[2] = __floats2half2_rn(v1.x, v1.y);
            o[3] = __floats2half2_rn(v1.z, v1.w);
            *reinterpret_cast<uint4*>(&g_At[(size_t)row * KK + k0]) =
                *reinterpret_cast<const uint4*>(o);
        }
    } else {
        // ---- W pack: tile 64k x 32c, write coalesced half2 rows ----
        const int wb = blockIdx.x - PACKA_BLOCKS;
        const int k0 = (wb & 31) * 64;            // 32 k-tiles
        const int c0 = (wb >> 5) * 32;            // 128 c-tiles
        #pragma unroll
        for (int i = 0; i < 8; i++) {
            const int idx = tid + 256 * i;        // 0..2047
            const int cl = idx & 31;
            const int kl = idx >> 5;              // 0..63
            const int k = k0 + kl;
            const int c = c0 + cl;
            tile[cl][kl] = (k < II) ? Wx[(size_t)k * NNP + c]
                                    : Wh[(size_t)(k - II) * NNP + c];
        }
        __syncthreads();
        #pragma unroll
        for (int i = 0; i < 4; i++) {
            const int idx = tid + 256 * i;        // 0..1023
            const int k2 = idx & 31;              // half2 unit within row
            const int cl = idx >> 5;              // 0..31
            const int c = c0 + cl;
            const int g = c >> 10;
            const int j = c & 1023;
            const int np = 4 * j + g;
            const __half2 hv = __floats2half2_rn(tile[cl][2 * k2], tile[cl][2 * k2 + 1]);
            *reinterpret_cast<__half2*>(&g_Wt[(size_t)np * KK + k0 + 2 * k2]) = hv;
        }
    }
}

// ------------------------------------------------------------ GEMM kernel ---
// R8 structure (best known) + register-free early full-wait: the wait for
// chunk kc+1 sits between arrive(free) and s3's mma_all, draining under the
// 64 queued HMMAs of s2+s3 instead of gating next chunk's ldmatrix burst.
// mbars: [0..2] full[s] (cnt 128, async arrivals), [3..5] free[s] (cnt 4),
//        [6] cin ready (cnt 128, async arrivals)
__global__ __launch_bounds__(THREADS, 2) void lstm_gemm_kernel(
    const float* __restrict__ cin, const float* __restrict__ bx,
    float* __restrict__ out, int write_c) {
    extern __shared__ char dynsmem[];
    __shared__ __align__(8) uint64_t s_mb[7];
    const uint32_t sbase = smem_u32(dynsmem);
    const uint32_t mb0 = smem_u32(&s_mb[0]);

    const int tid = threadIdx.x;
    const int wid = tid >> 5;
    const int lane = tid & 31;
    const int tn = blockIdx.x;       // N tile (0..31), 128 packed cols
    const int tm = blockIdx.y;       // M tile (0..63)
    const int row0 = tm * BM;
    const int n0 = tn * BN;

    if (tid == 0) {
        #pragma unroll
        for (int s = 0; s < 3; s++) mbar_init(mb0 + 8 * s, 128);        // full
        #pragma unroll
        for (int s = 0; s < 3; s++) mbar_init(mb0 + 8 * (3 + s), 4);    // free
        mbar_init(mb0 + 8 * 6, 128);                                    // cin
    }
    __syncthreads();

    float acc[4][8][4] = {};          // warp tile 64x64

    // ---- producer: fill kf (stage kf%3); kf==NCHUNK fills cin into stage 2 ----
    auto producer = [&](int kf) {
        if (kf < NCHUNK) {
            const int st = kf % NSTAGE;
            if (kf >= NSTAGE) mbar_wait(mb0 + 8 * (3 + st), (uint32_t)((kf / NSTAGE - 1) & 1));
            const uint32_t sa = sbase + st * STAGE_BYTES;
            const uint32_t sb = sa + ASTAGE_BYTES;
            const __half* gA = g_At + (size_t)row0 * KK + kf * BK;
            #pragma unroll
            for (int i = 0; i < 8; i++) {
                const int idx = tid + THREADS * i;   // 0..1023 (128 rows x 8 units)
                const int r = idx >> 3, uu = idx & 7;
                cp_async16(sa + r * 128 + ((uu ^ (r & 7)) << 4),
                           gA + (size_t)r * KK + uu * 8);
            }
            const __half* gB = g_Wt + (size_t)n0 * KK + kf * BK;
            #pragma unroll
            for (int i = 0; i < 8; i++) {
                const int idx = tid + THREADS * i;
                const int r = idx >> 3, uu = idx & 7;
                cp_async16(sb + r * 128 + ((uu ^ (r & 7)) << 4),
                           gB + (size_t)r * KK + uu * 8);
            }
            cp_async_arrive_noinc(mb0 + 8 * st);
        } else if (kf == NCHUNK) {
            // cin tile [128][32] f32 into stage-2 region (dead after use kc=29)
            mbar_wait(mb0 + 8 * (3 + 2), (uint32_t)((NCHUNK / NSTAGE - 1) & 1));
            const uint32_t cb = sbase + 2 * STAGE_BYTES;
            const float* gC = cin + (size_t)row0 * HH + tn * 32;
            #pragma unroll
            for (int i = 0; i < 8; i++) {
                const int v = tid + THREADS * i;     // 0..1023 (128 rows x 8 units)
                const int r = v >> 3, uu = v & 7;
                cp_async16(cb + r * 128 + ((uu ^ (r & 7)) << 4),
                           gC + (size_t)r * HH + uu * 4);
            }
            cp_async_arrive_noinc(mb0 + 8 * 6);
        }
    };

    producer(0);
    producer(1);

    const int wm0 = (wid >> 1) * 64;   // warp M origin (0 or 64)
    const int wn0 = (wid & 1) * 64;    // warp N origin (0 or 64)
    const int lsel = lane >> 3;        // ldmatrix matrix id (0..3)
    const int lrow8 = lane & 7;        // row within 8x8 matrix

    auto load_frags = [&](uint32_t sa, uint32_t sb, int s,
                          uint32_t (*afr)[4], uint32_t (*bfr)[4]) {
        #pragma unroll
        for (int mi = 0; mi < 4; mi++) {
            const int r = wm0 + mi * 16 + (lsel & 1) * 8 + lrow8;
            const uint32_t ku = (uint32_t)(s * 2 + (lsel >> 1));
            ldmatrix_x4(afr[mi], sa + r * 128 + ((ku ^ (uint32_t)(r & 7)) << 4));
        }
        #pragma unroll
        for (int fp = 0; fp < 4; fp++) {
            const int rn = wn0 + fp * 16 + (lsel >> 1) * 8 + lrow8;
            const uint32_t ku = (uint32_t)(s * 2 + (lsel & 1));
            ldmatrix_x4(bfr[fp], sb + rn * 128 + ((ku ^ (uint32_t)(rn & 7)) << 4));
        }
    };
    auto mma_all = [&](uint32_t (*afr)[4], uint32_t (*bfr)[4]) {
        #pragma unroll
        for (int mi = 0; mi < 4; mi++)
            #pragma unroll
            for (int f = 0; f < 8; f++)
                mma_fp16(acc[mi][f], afr[mi], &bfr[f >> 1][(f & 1) * 2]);
    };

    // prologue: chunk 0 must be resident before first loads
    mbar_wait(mb0 + 0, 0u);

    #pragma unroll 1
    for (int kc = 0; kc < NCHUNK; kc++) {
        const int st = kc % NSTAGE;
        const uint32_t sa = sbase + st * STAGE_BYTES;
        const uint32_t sb = sa + ASTAGE_BYTES;

        uint32_t afr[2][4][4];
        uint32_t bfr[2][4][4];
        load_frags(sa, sb, 0, afr[0], bfr[0]);
        load_frags(sa, sb, 1, afr[1], bfr[1]);
        mma_all(afr[0], bfr[0]);                 // s0
        producer(kc + 2);                        // free-wait hidden under s0 MMAs
        load_frags(sa, sb, 2, afr[0], bfr[0]);
        mma_all(afr[1], bfr[1]);                 // s1
        load_frags(sa, sb, 3, afr[1], bfr[1]);
        mma_all(afr[0], bfr[0]);                 // s2
        if (lane == 0) mbar_arrive(mb0 + 8 * (3 + st));   // stage reads done
        if (kc + 1 < NCHUNK)                     // early wait: drains under s2/s3 MMAs
            mbar_wait(mb0 + 8 * ((kc + 1) % NSTAGE),
                      (uint32_t)(((kc + 1) / NSTAGE) & 1));
        mma_all(afr[1], bfr[1]);                 // s3
    }

    mbar_wait(mb0 + 8 * 6, 0u);   // cin prefetch complete
    __syncthreads();              // all warps done with stages 0/1 before reuse

    // ---- fused LSTM epilogue ----
    float* smf = reinterpret_cast<float*>(dynsmem);   // h_s[128][33], c_s[128][33]
    const float* cin_s = reinterpret_cast<const float*>(dynsmem + 2 * STAGE_BYTES);
    const int odd = lane & 1;
    #pragma unroll
    for (int mi = 0; mi < 4; mi++) {
        #pragma unroll
        for (int f = 0; f < 8; f++) {
            const float c0 = acc[mi][f][0], c1 = acc[mi][f][1];
            const float c2 = acc[mi][f][2], c3 = acc[mi][f][3];
            const float x0 = __shfl_xor_sync(0xffffffffu, c0, 1);
            const float x1 = __shfl_xor_sync(0xffffffffu, c1, 1);
            const float x2 = __shfl_xor_sync(0xffffffffu, c2, 1);
            const float x3 = __shfl_xor_sync(0xffffffffu, c3, 1);
            // even lane: own (i,f), partner's (g,o); odd lane: row+8, own (g,o)
            const int lrow = wm0 + mi * 16 + (lane >> 2) + (odd ? 8 : 0);
            const int jc = (wn0 >> 2) + f * 2 + ((lane & 3) >> 1);  // 0..31
            const int j = tn * 32 + jc;
            float gi = (odd ? x2 : c0) + bx[j];
            float gf = (odd ? x3 : c1) + bx[HH + j];
            float gg = (odd ? c2 : x0) + bx[2 * HH + j];
            float go = (odd ? c3 : x1) + bx[3 * HH + j];
            const float iv = sigmoid_fast(gi);
            const float fv = sigmoid_fast(gf);
            const float gv = tanh_fast(gg);
            const float ov = sigmoid_fast(go);
            // swizzled cin read (matches cp.async 16B-unit swizzle)
            const int u2 = jc >> 2;
            const float cv = cin_s[lrow * 32 + (((u2 ^ (lrow & 7)) << 2) | (jc & 3))];
            const float cn = fv * cv + iv * gv;
            const float hn = ov * tanh_fast(cn);
            smf[lrow * 33 + jc] = hn;
            smf[128 * 33 + lrow * 33 + jc] = cn;
        }
    }
    __syncthreads();

    // coalesced writeback (128 rows x 32 cols)
    #pragma unroll 1
    for (int i = tid; i < 128 * 32; i += THREADS) {
        const int r = i >> 5, jj = i & 31;
        out[(size_t)(row0 + r) * HH + tn * 32 + jj] = smf[r * 33 + jj];
    }
    if (write_c) {
        #pragma unroll 1
        for (int i = tid; i < 128 * 32; i += THREADS) {
            const int r = i >> 5, jj = i & 31;
            out[(size_t)BB * HH + (size_t)(row0 + r) * HH + tn * 32 + jj] =
                smf[128 * 33 + r * 33 + jj];
        }
    }
}

// ------------------------------------------------------------------ launch ---
extern "C" void kernel_launch(void* const* d_in, const int* in_sizes, int n_in,
                              void* d_out, int out_size) {
    const float* x  = (const float*)d_in[0];
    const float* h  = (const float*)d_in[1];
    const float* c  = (const float*)d_in[2];
    const float* Wx = (const float*)d_in[3];
    const float* bx = (const float*)d_in[4];
    const float* Wh = (const float*)d_in[5];
    float* out = (float*)d_out;
    (void)in_sizes; (void)n_in;

    const int write_c = (out_size >= 2 * BB * HH) ? 1 : 0;

    // 1) fused pack: A->fp16 (ILP2), W->fp16 transposed + gate-interleaved
    pack_fused_kernel<<<PACKA_BLOCKS + PACKW_BLOCKS, 256>>>(x, h, Wx, Wh);

    // 2) fp16 mma.sync GEMM (R8 structure + early wait), fused LSTM epilogue
    static int attr_set = 0;
    if (!attr_set) {
        cudaFuncSetAttribute(lstm_gemm_kernel,
                             cudaFuncAttributeMaxDynamicSharedMemorySize, DYN_SMEM);
        attr_set = 1;
    }
    lstm_gemm_kernel<<<dim3(NNP / BN, BB / BM), THREADS, DYN_SMEM>>>(c, bx, out, write_c);
}